// round 13
// baseline (speedup 1.0000x reference)
#include <cuda_runtime.h>
#include <cuda_bf16.h>
#include <cstdint>

#define N_NODES 100000
#define N_EDGES 800000
#define IN_CH 128
#define HID 128
#define OUT_CH 64

// ---------------- scratch (static device memory; no runtime alloc) ----------------
__device__ float g_A[N_NODES * HID];
__device__ float g_B[N_NODES * HID];
__device__ float g_dinv[N_NODES];
__device__ int   g_count[N_NODES + 1];
__device__ int   g_scan[N_NODES + 1];
__device__ int   g_rowptr[N_NODES + 1];
__device__ int   g_cursor[N_NODES];
__device__ int   g_srcs[N_EDGES];
__device__ int   g_bsum[128];
__device__ __align__(16) __nv_bfloat16 g_WhT[40960];
__device__ __align__(16) __nv_bfloat16 g_WlT[40960];

__device__ __forceinline__ void split1(float v, __nv_bfloat16& h, __nv_bfloat16& l) {
    h = __float2bfloat16_rn(v);
    l = __float2bfloat16_rn(v - __bfloat162float(h));
}

__device__ __forceinline__ uint32_t pack2(__nv_bfloat16 a, __nv_bfloat16 b) {
    __nv_bfloat162 v(a, b);
    return *reinterpret_cast<uint32_t*>(&v);
}

// ---------------- CSR build ----------------
__global__ void k_zero_count() {
    int i = blockIdx.x * blockDim.x + threadIdx.x;
    if (i <= N_NODES) g_count[i] = 0;
}

__global__ void k_hist(const int* __restrict__ dst) {
    int e = blockIdx.x * blockDim.x + threadIdx.x;
    if (e < N_EDGES) {
        int d = dst[e];
        if ((unsigned)d < (unsigned)N_NODES) atomicAdd(&g_count[d], 1);
    }
}

__global__ void k_dinv() {
    int i = blockIdx.x * blockDim.x + threadIdx.x;
    if (i < N_NODES) g_dinv[i] = rsqrtf((float)g_count[i] + 1.0f);
}

__global__ void k_scan1() {
    __shared__ int s[1024];
    int lt = threadIdx.x;
    int i = blockIdx.x * 1024 + lt;
    int v = (i <= N_NODES) ? g_count[i] : 0;
    s[lt] = v;
    __syncthreads();
    for (int off = 1; off < 1024; off <<= 1) {
        int t = (lt >= off) ? s[lt - off] : 0;
        __syncthreads();
        s[lt] += t;
        __syncthreads();
    }
    if (i <= N_NODES) g_scan[i] = s[lt];
    if (lt == 1023) g_bsum[blockIdx.x] = s[1023];
}

__global__ void k_scan2(int nb) {
    __shared__ int s[128];
    int lt = threadIdx.x;
    int v = (lt < nb) ? g_bsum[lt] : 0;
    s[lt] = v;
    __syncthreads();
    for (int off = 1; off < 128; off <<= 1) {
        int t = (lt >= off) ? s[lt - off] : 0;
        __syncthreads();
        s[lt] += t;
        __syncthreads();
    }
    if (lt < nb) g_bsum[lt] = s[lt] - v;  // exclusive
}

__global__ void k_scan3() {
    int i = blockIdx.x * 1024 + threadIdx.x;
    if (i <= N_NODES) {
        int ex = g_scan[i] - g_count[i] + g_bsum[blockIdx.x];
        g_rowptr[i] = ex;
        if (i < N_NODES) g_cursor[i] = ex;
    }
}

__global__ void k_scatter(const int* __restrict__ ei) {
    int e = blockIdx.x * blockDim.x + threadIdx.x;
    if (e < N_EDGES) {
        int s = ei[e];
        int d = ei[N_EDGES + e];
        if ((unsigned)s < (unsigned)N_NODES && (unsigned)d < (unsigned)N_NODES) {
            int pos = atomicAdd(&g_cursor[d], 1);
            if ((unsigned)pos < (unsigned)N_EDGES) g_srcs[pos] = s;
        }
    }
}

// ---------------- W split+transpose ----------------
__global__ void k_wsplit(const float* __restrict__ W, int C, int dstOff) {
    int i = blockIdx.x * blockDim.x + threadIdx.x;
    if (i < 128 * C) {
        int k = i / C, n = i % C;
        __nv_bfloat16 h, l;
        split1(W[i], h, l);
        g_WhT[dstOff + n * 128 + k] = h;
        g_WlT[dstOff + n * 128 + k] = l;
    }
}

// ---------------- mma.sync bf16 GEMM ----------------
// 3-term split: D = Ah*Wh + Ah*Wl + Al*Wh.
// 512 threads = 4(M) x 4(N) warps. M-tile 128, full K=128, N=C.
// Per-warp: M32 x N(C/4). SROW=136 pad -> conflict-free b32 fragment loads.
#define SROW 136

__device__ __forceinline__ void mma_bf16(float* d, uint32_t a0, uint32_t a1, uint32_t a2,
                                         uint32_t a3, uint32_t b0, uint32_t b1) {
    asm volatile(
        "mma.sync.aligned.m16n8k16.row.col.f32.bf16.bf16.f32 "
        "{%0,%1,%2,%3}, {%4,%5,%6,%7}, {%8,%9}, {%0,%1,%2,%3};"
        : "+f"(d[0]), "+f"(d[1]), "+f"(d[2]), "+f"(d[3])
        : "r"(a0), "r"(a1), "r"(a2), "r"(a3), "r"(b0), "r"(b1));
}

template <int C>
__global__ __launch_bounds__(512, 1)
void k_gemm_mma(const float* __restrict__ X, const __nv_bfloat16* __restrict__ WhT,
                const __nv_bfloat16* __restrict__ WlT, float* __restrict__ Y) {
    constexpr int NF = C / 32;  // n8 frags per warp (4 for C=128, 2 for C=64)
    extern __shared__ char smem[];
    __nv_bfloat16* sAh = reinterpret_cast<__nv_bfloat16*>(smem);
    __nv_bfloat16* sAl = sAh + 128 * SROW;
    __nv_bfloat16* sBh = sAl + 128 * SROW;
    __nv_bfloat16* sBl = sBh + C * SROW;

    const int tid = threadIdx.x;
    const int rowBase = blockIdx.x * 128;

    // ---- A tile: convert 128 rows x 128 K fp32 -> bf16 hi/lo (16 warps hide latency) ----
    const float4* X4 = reinterpret_cast<const float4*>(X);
#pragma unroll
    for (int j = 0; j < 4; j++) {
        int idx = tid + j * 512;
        int row = idx >> 4, ch = idx & 15;
        int gr = rowBase + row;
        float4 v0 = make_float4(0.f, 0.f, 0.f, 0.f), v1 = v0;
        if (gr < N_NODES) {
            v0 = X4[gr * 32 + ch * 2];
            v1 = X4[gr * 32 + ch * 2 + 1];
        }
        __nv_bfloat16 h0, l0, h1, l1, h2, l2, h3, l3, h4, l4, h5, l5, h6, l6, h7, l7;
        split1(v0.x, h0, l0); split1(v0.y, h1, l1);
        split1(v0.z, h2, l2); split1(v0.w, h3, l3);
        split1(v1.x, h4, l4); split1(v1.y, h5, l5);
        split1(v1.z, h6, l6); split1(v1.w, h7, l7);
        uint4 hv = make_uint4(pack2(h0, h1), pack2(h2, h3), pack2(h4, h5), pack2(h6, h7));
        uint4 lv = make_uint4(pack2(l0, l1), pack2(l2, l3), pack2(l4, l5), pack2(l6, l7));
        *reinterpret_cast<uint4*>(&sAh[row * SROW + ch * 8]) = hv;
        *reinterpret_cast<uint4*>(&sAl[row * SROW + ch * 8]) = lv;
    }
    // ---- B tile: copy pre-split transposed weights [n][k] ----
#pragma unroll
    for (int j = 0; j < C * 16 / 512; j++) {
        int idx = tid + j * 512;
        int n = idx >> 4, c4 = idx & 15;
        uint4 vh = *reinterpret_cast<const uint4*>(WhT + n * 128 + c4 * 8);
        uint4 vl = *reinterpret_cast<const uint4*>(WlT + n * 128 + c4 * 8);
        *reinterpret_cast<uint4*>(&sBh[n * SROW + c4 * 8]) = vh;
        *reinterpret_cast<uint4*>(&sBl[n * SROW + c4 * 8]) = vl;
    }
    __syncthreads();

    // ---- compute: warp grid 4(M) x 4(N) ----
    const int warp = tid >> 5, lane = tid & 31;
    const int gid = lane >> 2, tig = lane & 3;
    const int mwarp = warp & 3, nwarp = warp >> 2;

    float acc[2][NF][4];
#pragma unroll
    for (int mf = 0; mf < 2; mf++)
#pragma unroll
        for (int nf = 0; nf < NF; nf++)
#pragma unroll
            for (int q = 0; q < 4; q++) acc[mf][nf][q] = 0.f;

#pragma unroll
    for (int pass = 0; pass < 3; pass++) {
        const __nv_bfloat16* pA = (pass == 2) ? sAl : sAh;
        const __nv_bfloat16* pB = (pass == 1) ? sBl : sBh;
#pragma unroll
        for (int ks = 0; ks < 8; ks++) {
            int k0 = ks * 16 + 2 * tig;
            uint32_t a[2][4];
#pragma unroll
            for (int mf = 0; mf < 2; mf++) {
                int r = mwarp * 32 + mf * 16 + gid;
                a[mf][0] = *reinterpret_cast<const uint32_t*>(&pA[r * SROW + k0]);
                a[mf][1] = *reinterpret_cast<const uint32_t*>(&pA[(r + 8) * SROW + k0]);
                a[mf][2] = *reinterpret_cast<const uint32_t*>(&pA[r * SROW + k0 + 8]);
                a[mf][3] = *reinterpret_cast<const uint32_t*>(&pA[(r + 8) * SROW + k0 + 8]);
            }
#pragma unroll
            for (int nf = 0; nf < NF; nf++) {
                int n = nwarp * (C / 4) + nf * 8 + gid;
                uint32_t b0 = *reinterpret_cast<const uint32_t*>(&pB[n * SROW + k0]);
                uint32_t b1 = *reinterpret_cast<const uint32_t*>(&pB[n * SROW + k0 + 8]);
#pragma unroll
                for (int mf = 0; mf < 2; mf++)
                    mma_bf16(acc[mf][nf], a[mf][0], a[mf][1], a[mf][2], a[mf][3], b0, b1);
            }
        }
    }

    // ---- epilogue ----
#pragma unroll
    for (int mf = 0; mf < 2; mf++) {
        int r = rowBase + mwarp * 32 + mf * 16 + gid;
#pragma unroll
        for (int nf = 0; nf < NF; nf++) {
            int col = nwarp * (C / 4) + nf * 8 + 2 * tig;
            float* d = acc[mf][nf];
            if (r < N_NODES)
                *reinterpret_cast<float2*>(&Y[r * C + col]) = make_float2(d[0], d[1]);
            if (r + 8 < N_NODES)
                *reinterpret_cast<float2*>(&Y[(r + 8) * C + col]) = make_float2(d[2], d[3]);
        }
    }
}

template <int C>
constexpr int gemm_mma_smem() { return (128 * SROW * 2 + C * SROW * 2) * 2; }

// ---------------- Aggregation with shfl-batched edge indices ----------------
template <int C, bool RELU>
__global__ void k_agg(const float* __restrict__ H, const float* __restrict__ bias,
                      float* __restrict__ out) {
    constexpr int LANES = C / 4;  // 32 or 16
    int gtid = blockIdx.x * blockDim.x + threadIdx.x;
    int node = gtid / LANES;
    int lane = threadIdx.x % LANES;
    if (node >= N_NODES) return;

    const unsigned mask = (LANES == 32) ? 0xFFFFFFFFu
                                        : (0xFFFFu << (threadIdx.x & 16));

    int start = g_rowptr[node];
    int end   = g_rowptr[node + 1];
    float dn  = g_dinv[node];

    const float4* H4 = reinterpret_cast<const float4*>(H);
    float4 acc = make_float4(0.f, 0.f, 0.f, 0.f);

    for (int base = start; base < end; base += LANES) {
        int cnt = end - base;
        if (cnt > LANES) cnt = LANES;
        int sE = 0;
        float wE = 0.f;
        if (lane < cnt) {
            sE = g_srcs[base + lane];
            wE = g_dinv[sE];
        }
        for (int j = 0; j < cnt; j++) {
            int s  = __shfl_sync(mask, sE, j, LANES);
            float w = __shfl_sync(mask, wE, j, LANES);
            float4 v = H4[s * LANES + lane];
            acc.x = fmaf(w, v.x, acc.x);
            acc.y = fmaf(w, v.y, acc.y);
            acc.z = fmaf(w, v.z, acc.z);
            acc.w = fmaf(w, v.w, acc.w);
        }
    }

    float4 hs = H4[node * LANES + lane];
    float4 bv = reinterpret_cast<const float4*>(bias)[lane];
    acc.x = fmaf(fmaf(dn, hs.x, acc.x), dn, bv.x);
    acc.y = fmaf(fmaf(dn, hs.y, acc.y), dn, bv.y);
    acc.z = fmaf(fmaf(dn, hs.z, acc.z), dn, bv.z);
    acc.w = fmaf(fmaf(dn, hs.w, acc.w), dn, bv.w);
    if (RELU) {
        acc.x = fmaxf(acc.x, 0.f);
        acc.y = fmaxf(acc.y, 0.f);
        acc.z = fmaxf(acc.z, 0.f);
        acc.w = fmaxf(acc.w, 0.f);
    }
    reinterpret_cast<float4*>(out)[node * LANES + lane] = acc;
}

// ---------------- launch ----------------
extern "C" void kernel_launch(void* const* d_in, const int* in_sizes, int n_in,
                              void* d_out, int out_size) {
    const float* x  = (const float*)d_in[0];
    const int*   ei = (const int*)d_in[1];   // int32 (JAX x64 disabled)
    const float* W1 = (const float*)d_in[2];
    const float* b1 = (const float*)d_in[3];
    const float* W2 = (const float*)d_in[4];
    const float* b2 = (const float*)d_in[5];
    const float* W3 = (const float*)d_in[6];
    const float* b3 = (const float*)d_in[7];
    float* out = (float*)d_out;

    (void)in_sizes; (void)n_in; (void)out_size;

    constexpr int SM128 = gemm_mma_smem<128>();  // 139264
    constexpr int SM64  = gemm_mma_smem<64>();   // 104448
    cudaFuncSetAttribute(k_gemm_mma<128>, cudaFuncAttributeMaxDynamicSharedMemorySize, SM128);
    cudaFuncSetAttribute(k_gemm_mma<64>,  cudaFuncAttributeMaxDynamicSharedMemorySize, SM64);

    float* A; float* B; __nv_bfloat16* WhT; __nv_bfloat16* WlT;
    cudaGetSymbolAddress((void**)&A, g_A);
    cudaGetSymbolAddress((void**)&B, g_B);
    cudaGetSymbolAddress((void**)&WhT, g_WhT);
    cudaGetSymbolAddress((void**)&WlT, g_WlT);

    const int NB_SCAN = (N_NODES + 1 + 1023) / 1024;  // 98
    const int GEMM_BLOCKS = (N_NODES + 127) / 128;    // 782
    const int AGG_BLOCKS128 = (N_NODES * 32 + 255) / 256;
    const int AGG_BLOCKS64  = (N_NODES * 16 + 255) / 256;

    // weights + GEMM layer 1 first (profiled slot 4 = gemm<128>)
    k_wsplit<<<(128 * 128 + 255) / 256, 256>>>(W1, 128, 0);
    k_wsplit<<<(128 * 128 + 255) / 256, 256>>>(W2, 128, 16384);
    k_wsplit<<<(128 * 64 + 255) / 256, 256>>>(W3, 64, 32768);
    k_gemm_mma<128><<<GEMM_BLOCKS, 512, SM128>>>(x, WhT, WlT, A);

    // CSR build (independent of gemm layer 1)
    k_zero_count<<<(N_NODES + 1 + 255) / 256, 256>>>();
    k_hist<<<(N_EDGES + 255) / 256, 256>>>(ei + N_EDGES);
    k_dinv<<<(N_NODES + 255) / 256, 256>>>();
    k_scan1<<<NB_SCAN, 1024>>>();
    k_scan2<<<1, 128>>>(NB_SCAN);
    k_scan3<<<NB_SCAN, 1024>>>();
    k_scatter<<<(N_EDGES + 255) / 256, 256>>>(ei);

    // layer 1 agg, then layers 2-3
    k_agg<128, true><<<AGG_BLOCKS128, 256>>>(A, b1, B);
    k_gemm_mma<128><<<GEMM_BLOCKS, 512, SM128>>>(B, WhT + 16384, WlT + 16384, A);
    k_agg<128, true><<<AGG_BLOCKS128, 256>>>(A, b2, B);
    k_gemm_mma<64><<<GEMM_BLOCKS, 512, SM64>>>(B, WhT + 32768, WlT + 32768, A);
    k_agg<64, false><<<AGG_BLOCKS64, 256>>>(A, b3, out);
}

// round 14
// speedup vs baseline: 1.1068x; 1.1068x over previous
#include <cuda_runtime.h>
#include <cuda_bf16.h>
#include <cstdint>

#define N_NODES 100000
#define N_EDGES 800000
#define IN_CH 128
#define HID 128
#define OUT_CH 64

// ---------------- scratch (static device memory; no runtime alloc) ----------------
__device__ float g_A[N_NODES * HID];
__device__ float g_B[N_NODES * HID];
__device__ float g_dinv[N_NODES];
__device__ int   g_count[N_NODES + 1];
__device__ int   g_scan[N_NODES + 1];
__device__ int   g_rowptr[N_NODES + 1];
__device__ int   g_cursor[N_NODES];
__device__ int   g_srcs[N_EDGES];
__device__ int   g_bsum[128];
__device__ __align__(16) __nv_bfloat16 g_WhT[40960];
__device__ __align__(16) __nv_bfloat16 g_WlT[40960];

__device__ __forceinline__ void split1(float v, __nv_bfloat16& h, __nv_bfloat16& l) {
    h = __float2bfloat16_rn(v);
    l = __float2bfloat16_rn(v - __bfloat162float(h));
}

__device__ __forceinline__ uint32_t pack2(__nv_bfloat16 a, __nv_bfloat16 b) {
    __nv_bfloat162 v(a, b);
    return *reinterpret_cast<uint32_t*>(&v);
}

// ---------------- CSR build ----------------
__global__ void k_zero_count() {
    int i = blockIdx.x * blockDim.x + threadIdx.x;
    if (i <= N_NODES) g_count[i] = 0;
}

__global__ void k_hist(const int* __restrict__ dst) {
    int e = blockIdx.x * blockDim.x + threadIdx.x;
    if (e < N_EDGES) {
        int d = dst[e];
        if ((unsigned)d < (unsigned)N_NODES) atomicAdd(&g_count[d], 1);
    }
}

__global__ void k_scan1() {
    __shared__ int s[1024];
    int lt = threadIdx.x;
    int i = blockIdx.x * 1024 + lt;
    int v = (i <= N_NODES) ? g_count[i] : 0;
    s[lt] = v;
    __syncthreads();
    for (int off = 1; off < 1024; off <<= 1) {
        int t = (lt >= off) ? s[lt - off] : 0;
        __syncthreads();
        s[lt] += t;
        __syncthreads();
    }
    if (i <= N_NODES) g_scan[i] = s[lt];
    if (lt == 1023) g_bsum[blockIdx.x] = s[1023];
}

__global__ void k_scan2(int nb) {
    __shared__ int s[128];
    int lt = threadIdx.x;
    int v = (lt < nb) ? g_bsum[lt] : 0;
    s[lt] = v;
    __syncthreads();
    for (int off = 1; off < 128; off <<= 1) {
        int t = (lt >= off) ? s[lt - off] : 0;
        __syncthreads();
        s[lt] += t;
        __syncthreads();
    }
    if (lt < nb) g_bsum[lt] = s[lt] - v;  // exclusive
}

// rowptr/cursor + dinv fused (dinv only needs count)
__global__ void k_scan3() {
    int i = blockIdx.x * 1024 + threadIdx.x;
    if (i <= N_NODES) {
        int c = g_count[i];
        int ex = g_scan[i] - c + g_bsum[blockIdx.x];
        g_rowptr[i] = ex;
        if (i < N_NODES) {
            g_cursor[i] = ex;
            g_dinv[i] = rsqrtf((float)c + 1.0f);
        }
    }
}

__global__ void k_scatter(const int* __restrict__ ei) {
    int e = blockIdx.x * blockDim.x + threadIdx.x;
    if (e < N_EDGES) {
        int s = ei[e];
        int d = ei[N_EDGES + e];
        if ((unsigned)s < (unsigned)N_NODES && (unsigned)d < (unsigned)N_NODES) {
            int pos = atomicAdd(&g_cursor[d], 1);
            if ((unsigned)pos < (unsigned)N_EDGES) g_srcs[pos] = s;
        }
    }
}

// ---------------- W split+transpose ----------------
__global__ void k_wsplit(const float* __restrict__ W, int C, int dstOff) {
    int i = blockIdx.x * blockDim.x + threadIdx.x;
    if (i < 128 * C) {
        int k = i / C, n = i % C;
        __nv_bfloat16 h, l;
        split1(W[i], h, l);
        g_WhT[dstOff + n * 128 + k] = h;
        g_WlT[dstOff + n * 128 + k] = l;
    }
}

// ---------------- mma.sync bf16 GEMM with ldmatrix fragments ----------------
// 3-term split: D = Ah*Wh + Ah*Wl + Al*Wh.
// 256 threads = 4(M) x 2(N) warps. M-tile 128, full K=128, N=C.
// Per-warp M32 x N64 (C=128) / N32 (C=64). SROW=136 -> conflict-free LDSM.
#define SROW 136

__device__ __forceinline__ void mma_bf16(float* d, uint32_t a0, uint32_t a1, uint32_t a2,
                                         uint32_t a3, uint32_t b0, uint32_t b1) {
    asm volatile(
        "mma.sync.aligned.m16n8k16.row.col.f32.bf16.bf16.f32 "
        "{%0,%1,%2,%3}, {%4,%5,%6,%7}, {%8,%9}, {%0,%1,%2,%3};"
        : "+f"(d[0]), "+f"(d[1]), "+f"(d[2]), "+f"(d[3])
        : "r"(a0), "r"(a1), "r"(a2), "r"(a3), "r"(b0), "r"(b1));
}

#define LDSM4(r0, r1, r2, r3, addr) \
    asm volatile("ldmatrix.sync.aligned.m8n8.x4.shared.b16 {%0,%1,%2,%3}, [%4];" \
                 : "=r"(r0), "=r"(r1), "=r"(r2), "=r"(r3) : "r"(addr))

__device__ __forceinline__ uint32_t smem_u32(const void* p) {
    return (uint32_t)__cvta_generic_to_shared(p);
}

template <int C>
__global__ __launch_bounds__(256, 1)
void k_gemm_mma(const float* __restrict__ X, const __nv_bfloat16* __restrict__ WhT,
                const __nv_bfloat16* __restrict__ WlT, float* __restrict__ Y) {
    constexpr int NBLK = C / 64;        // 2 for C=128, 1 for C=64
    constexpr int NPAIR = NBLK * 2;     // 16-wide n pairs per warp
    extern __shared__ char smem[];
    __nv_bfloat16* sAh = reinterpret_cast<__nv_bfloat16*>(smem);
    __nv_bfloat16* sAl = sAh + 128 * SROW;
    __nv_bfloat16* sBh = sAl + 128 * SROW;
    __nv_bfloat16* sBl = sBh + C * SROW;

    const int tid = threadIdx.x;
    const int rowBase = blockIdx.x * 128;

    // ---- A tile: convert 128 rows x 128 K fp32 -> bf16 hi/lo ----
    const float4* X4 = reinterpret_cast<const float4*>(X);
#pragma unroll
    for (int j = 0; j < 8; j++) {
        int idx = tid + j * 256;
        int row = idx >> 4, ch = idx & 15;
        int gr = rowBase + row;
        float4 v0 = make_float4(0.f, 0.f, 0.f, 0.f), v1 = v0;
        if (gr < N_NODES) {
            v0 = X4[gr * 32 + ch * 2];
            v1 = X4[gr * 32 + ch * 2 + 1];
        }
        __nv_bfloat16 h0, l0, h1, l1, h2, l2, h3, l3, h4, l4, h5, l5, h6, l6, h7, l7;
        split1(v0.x, h0, l0); split1(v0.y, h1, l1);
        split1(v0.z, h2, l2); split1(v0.w, h3, l3);
        split1(v1.x, h4, l4); split1(v1.y, h5, l5);
        split1(v1.z, h6, l6); split1(v1.w, h7, l7);
        uint4 hv = make_uint4(pack2(h0, h1), pack2(h2, h3), pack2(h4, h5), pack2(h6, h7));
        uint4 lv = make_uint4(pack2(l0, l1), pack2(l2, l3), pack2(l4, l5), pack2(l6, l7));
        *reinterpret_cast<uint4*>(&sAh[row * SROW + ch * 8]) = hv;
        *reinterpret_cast<uint4*>(&sAl[row * SROW + ch * 8]) = lv;
    }
    // ---- B tile: copy pre-split transposed weights [n][k] ----
#pragma unroll
    for (int j = 0; j < C * 16 / 256; j++) {
        int idx = tid + j * 256;
        int n = idx >> 4, c4 = idx & 15;
        uint4 vh = *reinterpret_cast<const uint4*>(WhT + n * 128 + c4 * 8);
        uint4 vl = *reinterpret_cast<const uint4*>(WlT + n * 128 + c4 * 8);
        *reinterpret_cast<uint4*>(&sBh[n * SROW + c4 * 8]) = vh;
        *reinterpret_cast<uint4*>(&sBl[n * SROW + c4 * 8]) = vl;
    }
    __syncthreads();

    // ---- compute: warp grid 4(M) x 2(N) ----
    const int warp = tid >> 5, lane = tid & 31;
    const int gid = lane >> 2, tig = lane & 3;
    const int mwarp = warp & 3, nwarp = warp >> 2;

    // ldmatrix per-lane address offsets (element units, x2 for bytes)
    // A (x4, m16k16): row = r0 + (lane&15), koff = (lane>>4)*8
    const int aRow = (lane & 15);
    const int aK   = (lane >> 4) * 8;
    // B (x4 = two n8k16 frags): n = n0 + (lane>>4)*8 + (lane&7), koff = ((lane>>3)&1)*8
    const int bN   = (lane >> 4) * 8 + (lane & 7);
    const int bK   = ((lane >> 3) & 1) * 8;

    const uint32_t uAh = smem_u32(sAh), uAl = smem_u32(sAl);
    const uint32_t uBh = smem_u32(sBh), uBl = smem_u32(sBl);

    float acc[2][NBLK * 4][4];
#pragma unroll
    for (int mf = 0; mf < 2; mf++)
#pragma unroll
        for (int nf = 0; nf < NBLK * 4; nf++)
#pragma unroll
            for (int q = 0; q < 4; q++) acc[mf][nf][q] = 0.f;

#pragma unroll
    for (int pass = 0; pass < 3; pass++) {
        const uint32_t uA = (pass == 2) ? uAl : uAh;
        const uint32_t uB = (pass == 1) ? uBl : uBh;
        // per-mf A base addr (bytes)
        uint32_t aAddr[2];
#pragma unroll
        for (int mf = 0; mf < 2; mf++)
            aAddr[mf] = uA + (uint32_t)(((mwarp * 32 + mf * 16 + aRow) * SROW + aK) * 2);
        // per-pair B base addr
        uint32_t bAddr[NPAIR];
#pragma unroll
        for (int p = 0; p < NPAIR; p++) {
            int n0 = (p >> 1) * 64 + nwarp * 32 + (p & 1) * 16;
            bAddr[p] = uB + (uint32_t)(((n0 + bN) * SROW + bK) * 2);
        }
#pragma unroll
        for (int ks = 0; ks < 8; ks++) {
            uint32_t kOff = ks * 32;  // 16 bf16 = 32 bytes
            uint32_t a[2][4];
            LDSM4(a[0][0], a[0][1], a[0][2], a[0][3], aAddr[0] + kOff);
            LDSM4(a[1][0], a[1][1], a[1][2], a[1][3], aAddr[1] + kOff);
#pragma unroll
            for (int p = 0; p < NPAIR; p++) {
                uint32_t b0, b1, b2, b3;
                LDSM4(b0, b1, b2, b3, bAddr[p] + kOff);
                int nb = p >> 1;
                int nfBase = (p & 1) * 2;
#pragma unroll
                for (int mf = 0; mf < 2; mf++) {
                    mma_bf16(acc[mf][nb * 4 + nfBase + 0], a[mf][0], a[mf][1], a[mf][2], a[mf][3], b0, b1);
                    mma_bf16(acc[mf][nb * 4 + nfBase + 1], a[mf][0], a[mf][1], a[mf][2], a[mf][3], b2, b3);
                }
            }
        }
    }

    // ---- epilogue ----
#pragma unroll
    for (int mf = 0; mf < 2; mf++) {
        int r = rowBase + mwarp * 32 + mf * 16 + gid;
#pragma unroll
        for (int nb = 0; nb < NBLK; nb++) {
#pragma unroll
            for (int nf = 0; nf < 4; nf++) {
                int col = nb * 64 + nwarp * 32 + nf * 8 + 2 * tig;
                float* d = acc[mf][nb * 4 + nf];
                if (r < N_NODES)
                    *reinterpret_cast<float2*>(&Y[r * C + col]) = make_float2(d[0], d[1]);
                if (r + 8 < N_NODES)
                    *reinterpret_cast<float2*>(&Y[(r + 8) * C + col]) = make_float2(d[2], d[3]);
            }
        }
    }
}

template <int C>
constexpr int gemm_mma_smem() { return (128 * SROW * 2 + C * SROW * 2) * 2; }

// ---------------- Aggregation with shfl-batched edge indices ----------------
template <int C, bool RELU>
__global__ void k_agg(const float* __restrict__ H, const float* __restrict__ bias,
                      float* __restrict__ out) {
    constexpr int LANES = C / 4;  // 32 or 16
    int gtid = blockIdx.x * blockDim.x + threadIdx.x;
    int node = gtid / LANES;
    int lane = threadIdx.x % LANES;
    if (node >= N_NODES) return;

    const unsigned mask = (LANES == 32) ? 0xFFFFFFFFu
                                        : (0xFFFFu << (threadIdx.x & 16));

    int start = g_rowptr[node];
    int end   = g_rowptr[node + 1];
    float dn  = g_dinv[node];

    const float4* H4 = reinterpret_cast<const float4*>(H);
    float4 acc = make_float4(0.f, 0.f, 0.f, 0.f);

    for (int base = start; base < end; base += LANES) {
        int cnt = end - base;
        if (cnt > LANES) cnt = LANES;
        int sE = 0;
        float wE = 0.f;
        if (lane < cnt) {
            sE = g_srcs[base + lane];
            wE = g_dinv[sE];
        }
        for (int j = 0; j < cnt; j++) {
            int s  = __shfl_sync(mask, sE, j, LANES);
            float w = __shfl_sync(mask, wE, j, LANES);
            float4 v = H4[s * LANES + lane];
            acc.x = fmaf(w, v.x, acc.x);
            acc.y = fmaf(w, v.y, acc.y);
            acc.z = fmaf(w, v.z, acc.z);
            acc.w = fmaf(w, v.w, acc.w);
        }
    }

    float4 hs = H4[node * LANES + lane];
    float4 bv = reinterpret_cast<const float4*>(bias)[lane];
    acc.x = fmaf(fmaf(dn, hs.x, acc.x), dn, bv.x);
    acc.y = fmaf(fmaf(dn, hs.y, acc.y), dn, bv.y);
    acc.z = fmaf(fmaf(dn, hs.z, acc.z), dn, bv.z);
    acc.w = fmaf(fmaf(dn, hs.w, acc.w), dn, bv.w);
    if (RELU) {
        acc.x = fmaxf(acc.x, 0.f);
        acc.y = fmaxf(acc.y, 0.f);
        acc.z = fmaxf(acc.z, 0.f);
        acc.w = fmaxf(acc.w, 0.f);
    }
    reinterpret_cast<float4*>(out)[node * LANES + lane] = acc;
}

// ---------------- launch ----------------
extern "C" void kernel_launch(void* const* d_in, const int* in_sizes, int n_in,
                              void* d_out, int out_size) {
    const float* x  = (const float*)d_in[0];
    const int*   ei = (const int*)d_in[1];   // int32 (JAX x64 disabled)
    const float* W1 = (const float*)d_in[2];
    const float* b1 = (const float*)d_in[3];
    const float* W2 = (const float*)d_in[4];
    const float* b2 = (const float*)d_in[5];
    const float* W3 = (const float*)d_in[6];
    const float* b3 = (const float*)d_in[7];
    float* out = (float*)d_out;

    (void)in_sizes; (void)n_in; (void)out_size;

    constexpr int SM128 = gemm_mma_smem<128>();  // 139264
    constexpr int SM64  = gemm_mma_smem<64>();   // 104448
    cudaFuncSetAttribute(k_gemm_mma<128>, cudaFuncAttributeMaxDynamicSharedMemorySize, SM128);
    cudaFuncSetAttribute(k_gemm_mma<64>,  cudaFuncAttributeMaxDynamicSharedMemorySize, SM64);

    float* A; float* B; __nv_bfloat16* WhT; __nv_bfloat16* WlT;
    cudaGetSymbolAddress((void**)&A, g_A);
    cudaGetSymbolAddress((void**)&B, g_B);
    cudaGetSymbolAddress((void**)&WhT, g_WhT);
    cudaGetSymbolAddress((void**)&WlT, g_WlT);

    const int NB_SCAN = (N_NODES + 1 + 1023) / 1024;  // 98
    const int GEMM_BLOCKS = (N_NODES + 127) / 128;    // 782
    const int AGG_BLOCKS128 = (N_NODES * 32 + 255) / 256;
    const int AGG_BLOCKS64  = (N_NODES * 16 + 255) / 256;

    // weights + GEMM layer 1 first (profiled slot 4 = gemm<128>)
    k_wsplit<<<(128 * 128 + 255) / 256, 256>>>(W1, 128, 0);
    k_wsplit<<<(128 * 128 + 255) / 256, 256>>>(W2, 128, 16384);
    k_wsplit<<<(128 * 64 + 255) / 256, 256>>>(W3, 64, 32768);
    k_gemm_mma<128><<<GEMM_BLOCKS, 256, SM128>>>(x, WhT, WlT, A);

    // CSR build (independent of gemm layer 1)
    k_zero_count<<<(N_NODES + 1 + 255) / 256, 256>>>();
    k_hist<<<(N_EDGES + 255) / 256, 256>>>(ei + N_EDGES);
    k_scan1<<<NB_SCAN, 1024>>>();
    k_scan2<<<1, 128>>>(NB_SCAN);
    k_scan3<<<NB_SCAN, 1024>>>();
    k_scatter<<<(N_EDGES + 255) / 256, 256>>>(ei);

    // layer 1 agg, then layers 2-3
    k_agg<128, true><<<AGG_BLOCKS128, 256>>>(A, b1, B);
    k_gemm_mma<128><<<GEMM_BLOCKS, 256, SM128>>>(B, WhT + 16384, WlT + 16384, A);
    k_agg<128, true><<<AGG_BLOCKS128, 256>>>(A, b2, B);
    k_gemm_mma<64><<<GEMM_BLOCKS, 256, SM64>>>(B, WhT + 32768, WlT + 32768, A);
    k_agg<64, false><<<AGG_BLOCKS64, 256>>>(A, b3, out);
}